// round 5
// baseline (speedup 1.0000x reference)
#include <cuda_runtime.h>
#include <cstdint>

#define N_NODES 20000
#define N_EDGES 100000
#define DN 256
#define DE 256
#define DH 512
#define NLAYERS 2

// ---------------- scratch (device globals: allocation-free) ----------------
__device__ float g_m1 [(size_t)N_EDGES * DH];   // relu(concat @ W1a + b1a)
__device__ float g_e  [(size_t)N_EDGES * DE];   // edge features between layers
__device__ float g_x  [(size_t)N_NODES * DN];   // node features between layers
__device__ float g_agg[(size_t)N_NODES * DH];   // segment-sum accumulator
__device__ float g_h  [(size_t)N_NODES * DH];   // relu(agg_norm @ W2a + b2a)
__device__ float g_cnt[N_NODES];                // in-degree counts

typedef unsigned long long u64;

// ---------------- packed f32x2 helpers (SASS FFMA2 path) ----------------
__device__ __forceinline__ u64 pack2(float lo, float hi) {
    u64 r;
    asm("mov.b64 %0, {%1, %2};" : "=l"(r) : "f"(lo), "f"(hi));
    return r;
}
__device__ __forceinline__ float2 unpack2(u64 v) {
    float2 r;
    asm("mov.b64 {%0, %1}, %2;" : "=f"(r.x), "=f"(r.y) : "l"(v));
    return r;
}
__device__ __forceinline__ void ffma2(u64& d, u64 a, u64 b) {
    asm("fma.rn.f32x2 %0, %1, %2, %0;" : "+l"(d) : "l"(a), "l"(b));
}

// Inner product body over one BK=16 shared tile.
// acc[i][j2] packs output cols (2*j2, 2*j2+1); B pairs come free from LDS.128.
#define MM_BODY()                                                          \
    _Pragma("unroll")                                                      \
    for (int kk = 0; kk < 16; ++kk) {                                      \
        float4 a0 = *(const float4*)&As[kk][tm * 8];                       \
        float4 a1 = *(const float4*)&As[kk][tm * 8 + 4];                   \
        ulonglong2 b01 = *(const ulonglong2*)&Bs[kk][tn * 8];              \
        ulonglong2 b23 = *(const ulonglong2*)&Bs[kk][tn * 8 + 4];          \
        u64 bb0 = b01.x, bb1 = b01.y, bb2 = b23.x, bb3 = b23.y;            \
        float av[8] = {a0.x, a0.y, a0.z, a0.w, a1.x, a1.y, a1.z, a1.w};    \
        _Pragma("unroll")                                                  \
        for (int i = 0; i < 8; ++i) {                                      \
            u64 ar = pack2(av[i], av[i]);                                  \
            ffma2(acc[i][0], ar, bb0);                                     \
            ffma2(acc[i][1], ar, bb1);                                     \
            ffma2(acc[i][2], ar, bb2);                                     \
            ffma2(acc[i][3], ar, bb3);                                     \
        }                                                                  \
    }

#define ZERO_ACC()                                                         \
    u64 acc[8][4];                                                         \
    _Pragma("unroll")                                                      \
    for (int i = 0; i < 8; ++i)                                            \
        _Pragma("unroll")                                                  \
        for (int j = 0; j < 4; ++j) acc[i][j] = 0ull;

#define UNPACK_RELU(o, i, bset)                                            \
    float o[8];                                                            \
    _Pragma("unroll")                                                      \
    for (int j2 = 0; j2 < 4; ++j2) {                                       \
        float2 v = unpack2(acc[i][j2]);                                    \
        o[2 * j2]     = fmaxf(v.x + bset[2 * j2], 0.f);                    \
        o[2 * j2 + 1] = fmaxf(v.y + bset[2 * j2 + 1], 0.f);                \
    }

// ---------------- small utility kernels ----------------
__global__ void zero_cnt_kernel() {
    int i = blockIdx.x * blockDim.x + threadIdx.x;
    if (i < N_NODES) g_cnt[i] = 0.f;
}
__global__ void zero_agg_kernel() {
    int i = blockIdx.x * blockDim.x + threadIdx.x;
    if (i < N_NODES * DH / 4)
        ((float4*)g_agg)[i] = make_float4(0.f, 0.f, 0.f, 0.f);
}
__global__ void count_kernel(const int* __restrict__ dstI) {
    int e = blockIdx.x * blockDim.x + threadIdx.x;
    if (e < N_EDGES) atomicAdd(&g_cnt[dstI[e]], 1.f);
}

// ============================================================================
// GEMM1: m1 = relu([x[dst] | e | x[src]] @ W1a + b1a)   (E x 768)@(768 x 512)
// A rows are gathered on the fly. Grid: (4 N-tiles, 782 M-tiles).
// ============================================================================
__global__ void __launch_bounds__(256, 2) gemm1_kernel(
    const float* __restrict__ xin, const float* __restrict__ ein,
    const int* __restrict__ srcI, const int* __restrict__ dstI,
    const float* __restrict__ W, const float* __restrict__ bias)
{
    __shared__ float As[16][128];
    __shared__ float Bs[16][128];
    __shared__ int sDst[128], sSrc[128];

    const int tid = threadIdx.x;
    const int n0 = blockIdx.x * 128;
    const int m0 = blockIdx.y * 128;
    const int tm = tid >> 4, tn = tid & 15;

    if (tid < 128) {
        int r = m0 + tid;
        sDst[tid] = (r < N_EDGES) ? dstI[r] : 0;
        sSrc[tid] = (r < N_EDGES) ? srcI[r] : 0;
    }
    __syncthreads();

    ZERO_ACC();

    const int am = tid >> 2, ak = (tid & 3) << 2;
    const int bk = tid >> 4, bn = (tid & 15) << 2;

    for (int k0 = 0; k0 < 2 * DN + DE; k0 += 16) {
#pragma unroll
        for (int h = 0; h < 2; ++h) {
            int lm = am + h * 64;
            int r = m0 + lm;
            float4 v = make_float4(0.f, 0.f, 0.f, 0.f);
            if (r < N_EDGES) {
                int kg = k0 + ak;
                const float* p;
                if (kg < DN)            p = xin + (size_t)sDst[lm] * DN + kg;
                else if (kg < DN + DE)  p = ein + (size_t)r * DE + (kg - DN);
                else                    p = xin + (size_t)sSrc[lm] * DN + (kg - DN - DE);
                v = *(const float4*)p;
            }
            As[ak + 0][lm] = v.x; As[ak + 1][lm] = v.y;
            As[ak + 2][lm] = v.z; As[ak + 3][lm] = v.w;
        }
        {
            const float* wp = W + (size_t)(k0 + bk) * DH + n0;
            *(float4*)&Bs[bk][bn]      = *(const float4*)(wp + bn);
            *(float4*)&Bs[bk][bn + 64] = *(const float4*)(wp + bn + 64);
        }
        __syncthreads();
        MM_BODY();
        __syncthreads();
    }

    float bset[8];
    {
        float4 b0 = *(const float4*)(bias + n0 + tn * 8);
        float4 b1 = *(const float4*)(bias + n0 + tn * 8 + 4);
        bset[0] = b0.x; bset[1] = b0.y; bset[2] = b0.z; bset[3] = b0.w;
        bset[4] = b1.x; bset[5] = b1.y; bset[6] = b1.z; bset[7] = b1.w;
    }
#pragma unroll
    for (int i = 0; i < 8; ++i) {
        int r = m0 + tm * 8 + i;
        if (r >= N_EDGES) continue;
        UNPACK_RELU(o, i, bset);
        float* op = g_m1 + (size_t)r * DH + n0 + tn * 8;
        *(float4*)op       = make_float4(o[0], o[1], o[2], o[3]);
        *(float4*)(op + 4) = make_float4(o[4], o[5], o[6], o[7]);
    }
}

// ============================================================================
// GEMM2: m2 = relu(m1 @ W1b + b1b)   (E x 512)@(512 x 1280)
// Epilogue by column region: [0,512)+[768,1280) -> atomicAdd into g_agg[dst]
// (sum of the two relu branches == xm, order-free); [512,768) -> new_e.
// Grid: (10 N-tiles, 782 M-tiles).
// ============================================================================
__global__ void __launch_bounds__(256, 2) gemm2_kernel(
    const int* __restrict__ dstI,
    const float* __restrict__ W, const float* __restrict__ bias,
    float* __restrict__ eout)
{
    __shared__ float As[16][128];
    __shared__ float Bs[16][128];
    __shared__ int sDst[128];

    const int tid = threadIdx.x;
    const int n0 = blockIdx.x * 128;
    const int m0 = blockIdx.y * 128;
    const int tm = tid >> 4, tn = tid & 15;
    const int ldW = 2 * DH + DE;  // 1280

    if (tid < 128) {
        int r = m0 + tid;
        sDst[tid] = (r < N_EDGES) ? dstI[r] : 0;
    }
    __syncthreads();

    ZERO_ACC();

    const int am = tid >> 2, ak = (tid & 3) << 2;
    const int bk = tid >> 4, bn = (tid & 15) << 2;

    for (int k0 = 0; k0 < DH; k0 += 16) {
#pragma unroll
        for (int h = 0; h < 2; ++h) {
            int lm = am + h * 64;
            int r = m0 + lm;
            float4 v = (r < N_EDGES)
                ? *(const float4*)(g_m1 + (size_t)r * DH + k0 + ak)
                : make_float4(0.f, 0.f, 0.f, 0.f);
            As[ak + 0][lm] = v.x; As[ak + 1][lm] = v.y;
            As[ak + 2][lm] = v.z; As[ak + 3][lm] = v.w;
        }
        {
            const float* wp = W + (size_t)(k0 + bk) * ldW + n0;
            *(float4*)&Bs[bk][bn]      = *(const float4*)(wp + bn);
            *(float4*)&Bs[bk][bn + 64] = *(const float4*)(wp + bn + 64);
        }
        __syncthreads();
        MM_BODY();
        __syncthreads();
    }

    float bset[8];
    {
        float4 b0 = *(const float4*)(bias + n0 + tn * 8);
        float4 b1 = *(const float4*)(bias + n0 + tn * 8 + 4);
        bset[0] = b0.x; bset[1] = b0.y; bset[2] = b0.z; bset[3] = b0.w;
        bset[4] = b1.x; bset[5] = b1.y; bset[6] = b1.z; bset[7] = b1.w;
    }
    const int ncol = n0 + tn * 8;
#pragma unroll
    for (int i = 0; i < 8; ++i) {
        int r = m0 + tm * 8 + i;
        if (r >= N_EDGES) continue;
        UNPACK_RELU(o, i, bset);
        if (n0 < DH) {                     // xm part 1 -> segment sum
            float* ap = g_agg + (size_t)sDst[tm * 8 + i] * DH + ncol;
#pragma unroll
            for (int j = 0; j < 8; ++j) atomicAdd(ap + j, o[j]);
        } else if (n0 < DH + DE) {         // new_e
            float* op = eout + (size_t)r * DE + (ncol - DH);
            *(float4*)op       = make_float4(o[0], o[1], o[2], o[3]);
            *(float4*)(op + 4) = make_float4(o[4], o[5], o[6], o[7]);
        } else {                           // xm part 2 -> segment sum
            float* ap = g_agg + (size_t)sDst[tm * 8 + i] * DH + (ncol - DH - DE);
#pragma unroll
            for (int j = 0; j < 8; ++j) atomicAdd(ap + j, o[j]);
        }
    }
}

// ============================================================================
// GEMM3: h = relu((agg * 1/max(cnt,1)) @ W2a + b2a)   (N x 512)@(512 x 512)
// Mean-normalization folded into the A-tile load. Grid: (4, 157).
// ============================================================================
__global__ void __launch_bounds__(256, 2) gemm3_kernel(
    const float* __restrict__ W, const float* __restrict__ bias)
{
    __shared__ float As[16][128];
    __shared__ float Bs[16][128];
    __shared__ float sInv[128];

    const int tid = threadIdx.x;
    const int n0 = blockIdx.x * 128;
    const int m0 = blockIdx.y * 128;
    const int tm = tid >> 4, tn = tid & 15;

    if (tid < 128) {
        int r = m0 + tid;
        float c = (r < N_NODES) ? g_cnt[r] : 1.f;
        sInv[tid] = 1.f / fmaxf(c, 1.f);
    }
    __syncthreads();

    ZERO_ACC();

    const int am = tid >> 2, ak = (tid & 3) << 2;
    const int bk = tid >> 4, bn = (tid & 15) << 2;

    for (int k0 = 0; k0 < DH; k0 += 16) {
#pragma unroll
        for (int h = 0; h < 2; ++h) {
            int lm = am + h * 64;
            int r = m0 + lm;
            float4 v = make_float4(0.f, 0.f, 0.f, 0.f);
            if (r < N_NODES) {
                v = *(const float4*)(g_agg + (size_t)r * DH + k0 + ak);
                float s = sInv[lm];
                v.x *= s; v.y *= s; v.z *= s; v.w *= s;
            }
            As[ak + 0][lm] = v.x; As[ak + 1][lm] = v.y;
            As[ak + 2][lm] = v.z; As[ak + 3][lm] = v.w;
        }
        {
            const float* wp = W + (size_t)(k0 + bk) * DH + n0;
            *(float4*)&Bs[bk][bn]      = *(const float4*)(wp + bn);
            *(float4*)&Bs[bk][bn + 64] = *(const float4*)(wp + bn + 64);
        }
        __syncthreads();
        MM_BODY();
        __syncthreads();
    }

    float bset[8];
    {
        float4 b0 = *(const float4*)(bias + n0 + tn * 8);
        float4 b1 = *(const float4*)(bias + n0 + tn * 8 + 4);
        bset[0] = b0.x; bset[1] = b0.y; bset[2] = b0.z; bset[3] = b0.w;
        bset[4] = b1.x; bset[5] = b1.y; bset[6] = b1.z; bset[7] = b1.w;
    }
#pragma unroll
    for (int i = 0; i < 8; ++i) {
        int r = m0 + tm * 8 + i;
        if (r >= N_NODES) continue;
        UNPACK_RELU(o, i, bset);
        float* op = g_h + (size_t)r * DH + n0 + tn * 8;
        *(float4*)op       = make_float4(o[0], o[1], o[2], o[3]);
        *(float4*)(op + 4) = make_float4(o[4], o[5], o[6], o[7]);
    }
}

// ============================================================================
// GEMM4: new_x = x + (h @ W2b + b2b)  [+ relu if not last layer]
// (N x 512)@(512 x 256). Residual folded into epilogue. Grid: (2, 157).
// ============================================================================
__global__ void __launch_bounds__(256, 2) gemm4_kernel(
    const float* __restrict__ xin,
    const float* __restrict__ W, const float* __restrict__ bias,
    float* __restrict__ xout, int do_relu)
{
    __shared__ float As[16][128];
    __shared__ float Bs[16][128];

    const int tid = threadIdx.x;
    const int n0 = blockIdx.x * 128;
    const int m0 = blockIdx.y * 128;
    const int tm = tid >> 4, tn = tid & 15;

    ZERO_ACC();

    const int am = tid >> 2, ak = (tid & 3) << 2;
    const int bk = tid >> 4, bn = (tid & 15) << 2;

    for (int k0 = 0; k0 < DH; k0 += 16) {
#pragma unroll
        for (int h = 0; h < 2; ++h) {
            int lm = am + h * 64;
            int r = m0 + lm;
            float4 v = (r < N_NODES)
                ? *(const float4*)(g_h + (size_t)r * DH + k0 + ak)
                : make_float4(0.f, 0.f, 0.f, 0.f);
            As[ak + 0][lm] = v.x; As[ak + 1][lm] = v.y;
            As[ak + 2][lm] = v.z; As[ak + 3][lm] = v.w;
        }
        {
            const float* wp = W + (size_t)(k0 + bk) * DN + n0;
            *(float4*)&Bs[bk][bn]      = *(const float4*)(wp + bn);
            *(float4*)&Bs[bk][bn + 64] = *(const float4*)(wp + bn + 64);
        }
        __syncthreads();
        MM_BODY();
        __syncthreads();
    }

    float bset[8];
    {
        float4 b0 = *(const float4*)(bias + n0 + tn * 8);
        float4 b1 = *(const float4*)(bias + n0 + tn * 8 + 4);
        bset[0] = b0.x; bset[1] = b0.y; bset[2] = b0.z; bset[3] = b0.w;
        bset[4] = b1.x; bset[5] = b1.y; bset[6] = b1.z; bset[7] = b1.w;
    }
    const int ncol = n0 + tn * 8;
#pragma unroll
    for (int i = 0; i < 8; ++i) {
        int r = m0 + tm * 8 + i;
        if (r >= N_NODES) continue;
        float4 x0 = *(const float4*)(xin + (size_t)r * DN + ncol);
        float4 x1 = *(const float4*)(xin + (size_t)r * DN + ncol + 4);
        float xv[8] = {x0.x, x0.y, x0.z, x0.w, x1.x, x1.y, x1.z, x1.w};
        float o[8];
#pragma unroll
        for (int j2 = 0; j2 < 4; ++j2) {
            float2 v = unpack2(acc[i][j2]);
            o[2 * j2]     = v.x + bset[2 * j2]     + xv[2 * j2];
            o[2 * j2 + 1] = v.y + bset[2 * j2 + 1] + xv[2 * j2 + 1];
        }
        if (do_relu) {
#pragma unroll
            for (int j = 0; j < 8; ++j) o[j] = fmaxf(o[j], 0.f);
        }
        float* op = xout + (size_t)r * DN + ncol;
        *(float4*)op       = make_float4(o[0], o[1], o[2], o[3]);
        *(float4*)(op + 4) = make_float4(o[4], o[5], o[6], o[7]);
    }
}

// ============================================================================
extern "C" void kernel_launch(void* const* d_in, const int* in_sizes, int n_in,
                              void* d_out, int out_size)
{
    (void)in_sizes; (void)n_in; (void)out_size;
    const float* node = (const float*)d_in[0];
    const float* edge = (const float*)d_in[1];
    const int*   eidx = (const int*)  d_in[2];
    const float* W1a  = (const float*)d_in[3];
    const float* b1a  = (const float*)d_in[4];
    const float* W1b  = (const float*)d_in[5];
    const float* b1b  = (const float*)d_in[6];
    const float* W2a  = (const float*)d_in[7];
    const float* b2a  = (const float*)d_in[8];
    const float* W2b  = (const float*)d_in[9];
    const float* b2b  = (const float*)d_in[10];
    float* out = (float*)d_out;

    const int* srcI = eidx;            // edges_indices[0]
    const int* dstI = eidx + N_EDGES;  // edges_indices[1]

    const int MT_E = (N_EDGES + 127) / 128;  // 782
    const int MT_N = (N_NODES + 127) / 128;  // 157

    // in-degree counts (same every layer)
    zero_cnt_kernel<<<(N_NODES + 255) / 256, 256>>>();
    count_kernel<<<(N_EDGES + 255) / 256, 256>>>(dstI);

    // device addresses of persistent buffers (taken via kernels' symbol use;
    // for host-side pointer arithmetic we only need them as launch args)
    for (int l = 0; l < NLAYERS; ++l) {
        zero_agg_kernel<<<(N_NODES * DH / 4 + 255) / 256, 256>>>();

        const float* xin = nullptr;
        const float* ein = nullptr;
        if (l == 0) { xin = node; ein = edge; }

        // For l>0 we must pass the device-global scratch addresses. Use a tiny
        // trampoline: kernels accept pointers, so fetch symbol addresses once.
        static float* p_gx = nullptr;
        static float* p_ge = nullptr;
        if (!p_gx) {
            void* tmp;
            cudaGetSymbolAddress(&tmp, g_x); p_gx = (float*)tmp;
            cudaGetSymbolAddress(&tmp, g_e); p_ge = (float*)tmp;
        }
        if (l > 0) { xin = p_gx; ein = p_ge; }

        gemm1_kernel<<<dim3(DH / 128, MT_E), 256>>>(
            xin, ein, srcI, dstI,
            W1a + (size_t)l * (2 * DN + DE) * DH, b1a + (size_t)l * DH);

        float* eout = (l == NLAYERS - 1) ? (out + (size_t)N_NODES * DN) : p_ge;
        gemm2_kernel<<<dim3((2 * DH + DE) / 128, MT_E), 256>>>(
            dstI,
            W1b + (size_t)l * DH * (2 * DH + DE), b1b + (size_t)l * (2 * DH + DE),
            eout);

        gemm3_kernel<<<dim3(DH / 128, MT_N), 256>>>(
            W2a + (size_t)l * DH * DH, b2a + (size_t)l * DH);

        float* xout = (l == NLAYERS - 1) ? out : p_gx;
        gemm4_kernel<<<dim3(DN / 128, MT_N), 256>>>(
            xin,
            W2b + (size_t)l * DH * DN, b2b + (size_t)l * DN,
            xout, (l < NLAYERS - 1) ? 1 : 0);
    }
}